// round 13
// baseline (speedup 1.0000x reference)
#include <cuda_runtime.h>
#include <cuda_bf16.h>
#include <cstdint>

// ============================================================================
// Problem dims
// ============================================================================
#define D_DIM   4096
#define M_ROWS  32768            // 8 * 4096

// GEMM tiling (bf16 HMMA; verified fastest config, round 4: 2726.5 us)
#define TILE_M   128
#define TILE_N   128
#define TILE_K   64              // bf16 elems per K-chunk (128 B/row in smem)
#define KCHUNKS  (D_DIM / TILE_K)   // 64
#define NSTAGE   3

// Tiled global layout: one (panel, kchunk) block = 128 rows x 128 B, contiguous
#define BLK_SZ     16384
#define STAGE_SZ   32768                         // A blk + B blk
#define BAR_OFF    (NSTAGE * STAGE_SZ)           // mbarriers after stages
#define SMEM_BYTES (BAR_OFF + 64)

// ============================================================================
// Scratch (device globals; no allocation anywhere)
// ============================================================================
__device__ __align__(256) __nv_bfloat16 g_q[(size_t)M_ROWS * D_DIM];  // 256 MB
__device__ __align__(256) __nv_bfloat16 g_w[(size_t)D_DIM * D_DIM];   // 32 MB
__device__ float  g_rs[M_ROWS];   // 1 / x_scale^2 per row
__device__ double g_ksum;

// ============================================================================
// Helpers
// ============================================================================
__device__ __forceinline__ uint32_t smem_to_u32(const void* smem_ptr) {
    uint32_t addr;
    asm("{ .reg .u64 tmp; cvta.to.shared.u64 tmp, %1; cvt.u32.u64 %0, tmp; }"
        : "=r"(addr) : "l"(smem_ptr));
    return addr;
}

// In-tile layout: (row 0..127, 16B unit 0..7) -> byte offset.
// u' = u ^ (row & 7): conflict-free ldmatrix phases (verified rounds 2-12).
__device__ __forceinline__ uint32_t sw_off(int row, int u) {
    return (uint32_t)(row * 128 + ((u ^ (row & 7)) << 4));
}

__device__ __forceinline__ void cp_bulk(uint32_t smem_dst, const void* gsrc,
                                        uint32_t bytes, uint32_t mbar) {
    asm volatile(
        "cp.async.bulk.shared::cluster.global.mbarrier::complete_tx::bytes "
        "[%0], [%1], %2, [%3];"
        :: "r"(smem_dst), "l"(__cvta_generic_to_global(gsrc)), "r"(bytes), "r"(mbar)
        : "memory");
}

// streaming 16B store (evict-first: don't pollute L2 with write-once data)
__device__ __forceinline__ void st_cs(void* gptr, uint4 v) {
    asm volatile("st.global.cs.v4.b32 [%0], {%1,%2,%3,%4};"
                 :: "l"(__cvta_generic_to_global(gptr)),
                    "r"(v.x), "r"(v.y), "r"(v.z), "r"(v.w) : "memory");
}

#define MBARRIER_INIT(addr, count) \
    asm volatile("mbarrier.init.shared.b64 [%0], %1;" \
                 :: "r"((uint32_t)(addr)), "r"((uint32_t)(count)) : "memory")

#define MBARRIER_ARRIVE_EXPECT_TX(addr, bytes) \
    asm volatile("mbarrier.arrive.expect_tx.shared.b64 _, [%0], %1;" \
                 :: "r"((uint32_t)(addr)), "r"((uint32_t)(bytes)) : "memory")

#define MBARRIER_WAIT_PARITY(mbar_smem_addr, phase_parity) do { \
    uint32_t _mbar = (uint32_t)(mbar_smem_addr); \
    uint32_t _parity = (uint32_t)(phase_parity); \
    uint32_t _done; \
    asm volatile( \
        "{\n\t" \
        ".reg .pred p;\n\t" \
        "mbarrier.try_wait.parity.acquire.cta.shared::cta.b64 p, [%1], %2;\n\t" \
        "selp.b32 %0, 1, 0, p;\n\t" \
        "}" \
        : "=r"(_done) : "r"(_mbar), "r"(_parity) : "memory"); \
    if (!_done) { \
        asm volatile( \
            "{\n\t" \
            ".reg .pred P1;\n\t" \
            "WAIT_LOOP_%=:\n\t" \
            "mbarrier.try_wait.parity.acquire.cta.shared::cta.b64 P1, [%0], %1, 0x989680;\n\t" \
            "@P1 bra.uni WAIT_DONE_%=;\n\t" \
            "bra.uni WAIT_LOOP_%=;\n\t" \
            "WAIT_DONE_%=:\n\t" \
            "}" \
            :: "r"(_mbar), "r"(_parity) : "memory"); \
    } \
} while(0)

__device__ __forceinline__ void ldm_x4(uint32_t* r, uint32_t addr) {
    asm volatile("ldmatrix.sync.aligned.m8n8.x4.shared.b16 {%0,%1,%2,%3}, [%4];"
                 : "=r"(r[0]), "=r"(r[1]), "=r"(r[2]), "=r"(r[3]) : "r"(addr));
}

__device__ __forceinline__ void mma_bf16(float* c, const uint32_t* a,
                                         uint32_t b0, uint32_t b1) {
    asm volatile(
        "mma.sync.aligned.m16n8k16.row.col.f32.bf16.bf16.f32 "
        "{%0,%1,%2,%3}, {%4,%5,%6,%7}, {%8,%9}, {%0,%1,%2,%3};"
        : "+f"(c[0]), "+f"(c[1]), "+f"(c[2]), "+f"(c[3])
        : "r"(a[0]), "r"(a[1]), "r"(a[2]), "r"(a[3]), "r"(b0), "r"(b1));
}

// ============================================================================
// Kernel 0/1: kernel-matrix mean (double accumulate)
// ============================================================================
__global__ void zero_kernel() { g_ksum = 0.0; }

__global__ void ksum_kernel(const float* __restrict__ k) {
    float s = 0.f;
    const float4* k4 = (const float4*)k;
    const int n4 = (D_DIM * D_DIM) / 4;
    for (int i = blockIdx.x * blockDim.x + threadIdx.x; i < n4; i += gridDim.x * blockDim.x) {
        float4 v = k4[i];
        s += v.x + v.y + v.z + v.w;
    }
#pragma unroll
    for (int o = 16; o > 0; o >>= 1) s += __shfl_xor_sync(0xffffffffu, s, o);
    __shared__ float sb[8];
    int wid = threadIdx.x >> 5, lid = threadIdx.x & 31;
    if (lid == 0) sb[wid] = s;
    __syncthreads();
    if (threadIdx.x == 0) {
        float t = 0.f;
        for (int i = 0; i < 8; i++) t += sb[i];
        atomicAdd(&g_ksum, (double)t);
    }
}

// ============================================================================
// Kernel 2: sign(kernel - mean), transposed to [f][d], into TILED+SWIZZLED g_w
// ============================================================================
__global__ void sign_kernel(const float* __restrict__ k) {
    __shared__ float t[32][33];
    float mean = (float)(g_ksum * (1.0 / 16777216.0));
    int d = blockIdx.y * 32 + threadIdx.y;
    int f = blockIdx.x * 32 + threadIdx.x;
    t[threadIdx.y][threadIdx.x] = k[(size_t)d * D_DIM + f];
    __syncthreads();
    int f2 = blockIdx.x * 32 + threadIdx.y;     // output row (n)
    int d2 = blockIdx.y * 32 + threadIdx.x;     // output col (k)
    float v = t[threadIdx.x][threadIdx.y] - mean;
    float s = (v > 0.f) ? 1.f : ((v < 0.f) ? -1.f : 0.f);
    int p  = f2 >> 7, r = f2 & 127;
    int kc = d2 >> 6, w = d2 & 63;
    int u  = w >> 3,  e = w & 7;
    *(__nv_bfloat16*)((char*)g_w + ((size_t)p * KCHUNKS + kc) * BLK_SZ
                      + sw_off(r, u) + e * 2) = __float2bfloat16_rn(s);
}

// ============================================================================
// Kernel 3: per-row RMSNorm + int8 fake-quant -> bf16 TILED+SWIZZLED g_q, 1/sc^2
// Streaming (evict-first) stores: g_q is write-once, keep L2 clean for GEMM.
// ============================================================================
__global__ void quant_kernel(const float* __restrict__ x) {
    int row = blockIdx.x;
    int tid = threadIdx.x;
    const float4* xr = (const float4*)(x + (size_t)row * D_DIM);
    float4 v[4];
    float ss = 0.f, am = 0.f;
#pragma unroll
    for (int i = 0; i < 4; i++) {
        v[i] = xr[tid * 4 + i];
        ss += v[i].x * v[i].x + v[i].y * v[i].y + v[i].z * v[i].z + v[i].w * v[i].w;
        am = fmaxf(am, fmaxf(fmaxf(fabsf(v[i].x), fabsf(v[i].y)),
                             fmaxf(fabsf(v[i].z), fabsf(v[i].w))));
    }
#pragma unroll
    for (int o = 16; o > 0; o >>= 1) {
        ss += __shfl_xor_sync(0xffffffffu, ss, o);
        am = fmaxf(am, __shfl_xor_sync(0xffffffffu, am, o));
    }
    __shared__ float s_ss[8], s_am[8];
    __shared__ float sh_rinv, sh_sc;
    int wid = tid >> 5, lid = tid & 31;
    if (lid == 0) { s_ss[wid] = ss; s_am[wid] = am; }
    __syncthreads();
    if (tid == 0) {
        float t = 0.f, m = 0.f;
        for (int i = 0; i < 8; i++) { t += s_ss[i]; m = fmaxf(m, s_am[i]); }
        float rinv = rsqrtf(t * (1.f / 4096.f) + 1e-5f);
        float amax = m * rinv;                       // == max|x_norm| (monotone)
        float sc = 127.f / fmaxf(amax, 1e-5f);
        sh_rinv = rinv; sh_sc = sc;
        g_rs[row] = 1.f / (sc * sc);
    }
    __syncthreads();
    float rinv = sh_rinv, sc = sh_sc;
    unsigned pk[8];
#pragma unroll
    for (int i = 0; i < 4; i++) {
        float a[4] = { v[i].x, v[i].y, v[i].z, v[i].w };
        unsigned short h[4];
#pragma unroll
        for (int j = 0; j < 4; j++) {
            float xn = a[j] * rinv;
            float r = rintf(xn * sc);                // round half-to-even == jnp.round
            r = fminf(fmaxf(r, -128.f), 127.f);
            h[j] = __bfloat16_as_ushort(__float2bfloat16_rn(r));   // exact
        }
        pk[i * 2]     = (unsigned)h[0] | ((unsigned)h[1] << 16);
        pk[i * 2 + 1] = (unsigned)h[2] | ((unsigned)h[3] << 16);
    }
    int p = row >> 7, r = row & 127;
    int kc = tid >> 2, u0 = (tid & 3) * 2;
    char* base = (char*)g_q + ((size_t)p * KCHUNKS + kc) * BLK_SZ;
    st_cs(base + sw_off(r, u0),     make_uint4(pk[0], pk[1], pk[2], pk[3]));
    st_cs(base + sw_off(r, u0 + 1), make_uint4(pk[4], pk[5], pk[6], pk[7]));
}

// ============================================================================
// Kernel 4: bf16 HMMA GEMM (round-4 verified best: 2 CTA/SM, 3-stage ring),
// with the refill ISSUE hoisted to the loop top: slot (kc+2)%3 was last read
// in iteration kc-1 (completed at that iteration's __syncthreads), so issuing
// right after this iteration's full-wait is safe and gives the copy one extra
// compute block of lead time.
// ============================================================================
__global__ void __launch_bounds__(256, 2) gemm_kernel(float* __restrict__ out) {
    extern __shared__ char smem[];
    const uint32_t sbase = smem_to_u32(smem);
    const uint32_t bar   = sbase + BAR_OFF;
    const int tid = threadIdx.x;
    const int wid = tid >> 5, lane = tid & 31;
    const int warp_m = wid >> 2;          // 0..1
    const int warp_n = wid & 3;           // 0..3
    const int m0 = blockIdx.y * TILE_M;
    const int n0 = blockIdx.x * TILE_N;

    const char* gA = (const char*)g_q + (size_t)blockIdx.y * KCHUNKS * BLK_SZ;
    const char* gB = (const char*)g_w + (size_t)blockIdx.x * KCHUNKS * BLK_SZ;

    if (tid == 0) {
#pragma unroll
        for (int s = 0; s < NSTAGE; s++) MBARRIER_INIT(bar + s * 8, 1);
    }
    __syncthreads();

    auto issue = [&](int kc, int s) {
        uint32_t mb = bar + s * 8;
        MBARRIER_ARRIVE_EXPECT_TX(mb, STAGE_SZ);
        cp_bulk(sbase + s * STAGE_SZ,          gA + (size_t)kc * BLK_SZ, BLK_SZ, mb);
        cp_bulk(sbase + s * STAGE_SZ + BLK_SZ, gB + (size_t)kc * BLK_SZ, BLK_SZ, mb);
    };

    if (tid == 0) {
#pragma unroll
        for (int s = 0; s < NSTAGE - 1; s++) issue(s, s);
    }

    float acc[4][4][4];
#pragma unroll
    for (int i = 0; i < 4; i++)
#pragma unroll
        for (int j = 0; j < 4; j++)
#pragma unroll
            for (int c = 0; c < 4; c++) acc[i][j][c] = 0.f;

    const int lr = (lane & 7) + ((lane >> 3) & 1) * 8;   // row within 16-row frag
    const int lk = lane >> 4;                             // which 16B half of k16

    for (int kc = 0; kc < KCHUNKS; kc++) {
        const int s = kc % NSTAGE;
        MBARRIER_WAIT_PARITY(bar + s * 8, (kc / NSTAGE) & 1);

        // Hoisted refill: chunk kc+2 into slot (kc+2)%3 == (kc-1)%3, whose
        // readers all finished at iteration kc-1's __syncthreads (kc>=1).
        if (tid == 0 && kc >= 1 && kc + NSTAGE - 1 < KCHUNKS)
            issue(kc + NSTAGE - 1, (kc + NSTAGE - 1) % NSTAGE);

        const uint32_t sa = sbase + s * STAGE_SZ;
        const uint32_t sb = sa + BLK_SZ;

#pragma unroll
        for (int ks = 0; ks < 4; ks++) {              // four k16 steps per 128B chunk
            const int ku = 2 * ks + lk;               // 16B unit index 0..7
            uint32_t afr[4][4];
#pragma unroll
            for (int mf = 0; mf < 4; mf++)
                ldm_x4(afr[mf], sa + sw_off(warp_m * 64 + mf * 16 + lr, ku));
            uint32_t bfr[2][4];
#pragma unroll
            for (int h = 0; h < 2; h++)
                ldm_x4(bfr[h], sb + sw_off(warp_n * 32 + h * 16 + lr, ku));
#pragma unroll
            for (int mf = 0; mf < 4; mf++) {
#pragma unroll
                for (int nf = 0; nf < 4; nf++) {
                    uint32_t b0 = bfr[nf >> 1][nf & 1];
                    uint32_t b1 = bfr[nf >> 1][(nf & 1) + 2];
                    mma_bf16(acc[mf][nf], afr[mf], b0, b1);
                }
            }
        }
        __syncthreads();   // all warps done reading slot s
        // kc==0 case: slot 2's first fill must wait for THIS sync (slot 2 has
        // never been read; but its first fill is chunk 2, issued in prologue).
        if (tid == 0 && kc == 0 && NSTAGE - 1 < KCHUNKS)
            issue(NSTAGE - 1, NSTAGE - 1);
    }

    // Epilogue: out = acc * (1/x_scale^2)   (acc holds exact integers in f32)
    const int group = lane >> 2, tig = lane & 3;
#pragma unroll
    for (int mf = 0; mf < 4; mf++) {
        int r0 = m0 + warp_m * 64 + mf * 16 + group;
        float rs0 = g_rs[r0];
        float rs1 = g_rs[r0 + 8];
        float* o0 = out + (size_t)r0 * D_DIM;
        float* o1 = out + (size_t)(r0 + 8) * D_DIM;
#pragma unroll
        for (int nf = 0; nf < 4; nf++) {
            int col = n0 + warp_n * 32 + nf * 8 + tig * 2;
            float2 v0, v1;
            v0.x = acc[mf][nf][0] * rs0;
            v0.y = acc[mf][nf][1] * rs0;
            v1.x = acc[mf][nf][2] * rs1;
            v1.y = acc[mf][nf][3] * rs1;
            *(float2*)(o0 + col) = v0;
            *(float2*)(o1 + col) = v1;
        }
    }
}

// ============================================================================
// kernel_launch: fully sequential (concurrency harmful per R9/R10; persistence
// harmful per R11). Round-4 configuration — the measured optimum.
// ============================================================================
extern "C" void kernel_launch(void* const* d_in, const int* in_sizes, int n_in,
                              void* d_out, int out_size) {
    const float* x    = (const float*)d_in[0];
    const float* kern = (const float*)d_in[1];
    if (n_in >= 2 && in_sizes[0] < in_sizes[1]) {    // x is the bigger tensor
        x    = (const float*)d_in[1];
        kern = (const float*)d_in[0];
    }

    cudaFuncSetAttribute(gemm_kernel, cudaFuncAttributeMaxDynamicSharedMemorySize, SMEM_BYTES);

    zero_kernel<<<1, 1>>>();
    ksum_kernel<<<1024, 256>>>(kern);
    sign_kernel<<<dim3(D_DIM / 32, D_DIM / 32), dim3(32, 32)>>>(kern);
    quant_kernel<<<M_ROWS, 256>>>(x);
    // grid.x fastest: 32 n-tiles share one A panel; g_w (32MB) stays L2-hot
    gemm_kernel<<<dim3(D_DIM / TILE_N, M_ROWS / TILE_M), 256, SMEM_BYTES>>>((float*)d_out);
}

// round 14
// speedup vs baseline: 1.0322x; 1.0322x over previous
#include <cuda_runtime.h>
#include <cuda_bf16.h>
#include <cstdint>

// ============================================================================
// Problem dims
// ============================================================================
#define D_DIM   4096
#define M_ROWS  32768            // 8 * 4096

// GEMM tiling (bf16 HMMA; verified fastest config: rounds 4 & 12)
#define TILE_M   128
#define TILE_N   128
#define TILE_K   64              // bf16 elems per K-chunk (128 B/row in smem)
#define KCHUNKS  (D_DIM / TILE_K)   // 64
#define NSTAGE   3

// Tiled global layout: one (panel, kchunk) block = 128 rows x 128 B, contiguous
#define BLK_SZ     16384
#define STAGE_SZ   32768                         // A blk + B blk
#define BAR_OFF    (NSTAGE * STAGE_SZ)           // mbarriers after stages
#define SMEM_BYTES (BAR_OFF + 64)

// ============================================================================
// Scratch (device globals; no allocation anywhere)
// ============================================================================
__device__ __align__(256) __nv_bfloat16 g_q[(size_t)M_ROWS * D_DIM];  // 256 MB
__device__ __align__(256) __nv_bfloat16 g_w[(size_t)D_DIM * D_DIM];   // 32 MB
__device__ float  g_rs[M_ROWS];   // 1 / x_scale^2 per row
__device__ double g_ksum;

// ============================================================================
// Helpers
// ============================================================================
__device__ __forceinline__ uint32_t smem_to_u32(const void* smem_ptr) {
    uint32_t addr;
    asm("{ .reg .u64 tmp; cvta.to.shared.u64 tmp, %1; cvt.u32.u64 %0, tmp; }"
        : "=r"(addr) : "l"(smem_ptr));
    return addr;
}

// In-tile layout: (row 0..127, 16B unit 0..7) -> byte offset.
// u' = u ^ (row & 7): conflict-free ldmatrix phases (verified rounds 2-13).
__device__ __forceinline__ uint32_t sw_off(int row, int u) {
    return (uint32_t)(row * 128 + ((u ^ (row & 7)) << 4));
}

__device__ __forceinline__ void cp_bulk(uint32_t smem_dst, const void* gsrc,
                                        uint32_t bytes, uint32_t mbar) {
    asm volatile(
        "cp.async.bulk.shared::cluster.global.mbarrier::complete_tx::bytes "
        "[%0], [%1], %2, [%3];"
        :: "r"(smem_dst), "l"(__cvta_generic_to_global(gsrc)), "r"(bytes), "r"(mbar)
        : "memory");
}

#define MBARRIER_INIT(addr, count) \
    asm volatile("mbarrier.init.shared.b64 [%0], %1;" \
                 :: "r"((uint32_t)(addr)), "r"((uint32_t)(count)) : "memory")

#define MBARRIER_ARRIVE_EXPECT_TX(addr, bytes) \
    asm volatile("mbarrier.arrive.expect_tx.shared.b64 _, [%0], %1;" \
                 :: "r"((uint32_t)(addr)), "r"((uint32_t)(bytes)) : "memory")

#define MBARRIER_WAIT_PARITY(mbar_smem_addr, phase_parity) do { \
    uint32_t _mbar = (uint32_t)(mbar_smem_addr); \
    uint32_t _parity = (uint32_t)(phase_parity); \
    uint32_t _done; \
    asm volatile( \
        "{\n\t" \
        ".reg .pred p;\n\t" \
        "mbarrier.try_wait.parity.acquire.cta.shared::cta.b64 p, [%1], %2;\n\t" \
        "selp.b32 %0, 1, 0, p;\n\t" \
        "}" \
        : "=r"(_done) : "r"(_mbar), "r"(_parity) : "memory"); \
    if (!_done) { \
        asm volatile( \
            "{\n\t" \
            ".reg .pred P1;\n\t" \
            "WAIT_LOOP_%=:\n\t" \
            "mbarrier.try_wait.parity.acquire.cta.shared::cta.b64 P1, [%0], %1, 0x989680;\n\t" \
            "@P1 bra.uni WAIT_DONE_%=;\n\t" \
            "bra.uni WAIT_LOOP_%=;\n\t" \
            "WAIT_DONE_%=:\n\t" \
            "}" \
            :: "r"(_mbar), "r"(_parity) : "memory"); \
    } \
} while(0)

__device__ __forceinline__ void ldm_x4(uint32_t* r, uint32_t addr) {
    asm volatile("ldmatrix.sync.aligned.m8n8.x4.shared.b16 {%0,%1,%2,%3}, [%4];"
                 : "=r"(r[0]), "=r"(r[1]), "=r"(r[2]), "=r"(r[3]) : "r"(addr));
}

__device__ __forceinline__ void mma_bf16(float* c, const uint32_t* a,
                                         uint32_t b0, uint32_t b1) {
    asm volatile(
        "mma.sync.aligned.m16n8k16.row.col.f32.bf16.bf16.f32 "
        "{%0,%1,%2,%3}, {%4,%5,%6,%7}, {%8,%9}, {%0,%1,%2,%3};"
        : "+f"(c[0]), "+f"(c[1]), "+f"(c[2]), "+f"(c[3])
        : "r"(a[0]), "r"(a[1]), "r"(a[2]), "r"(a[3]), "r"(b0), "r"(b1));
}

// ============================================================================
// Kernel 0/1: kernel-matrix mean (double accumulate)
// ============================================================================
__global__ void zero_kernel() { g_ksum = 0.0; }

__global__ void ksum_kernel(const float* __restrict__ k) {
    float s = 0.f;
    const float4* k4 = (const float4*)k;
    const int n4 = (D_DIM * D_DIM) / 4;
    for (int i = blockIdx.x * blockDim.x + threadIdx.x; i < n4; i += gridDim.x * blockDim.x) {
        float4 v = k4[i];
        s += v.x + v.y + v.z + v.w;
    }
#pragma unroll
    for (int o = 16; o > 0; o >>= 1) s += __shfl_xor_sync(0xffffffffu, s, o);
    __shared__ float sb[8];
    int wid = threadIdx.x >> 5, lid = threadIdx.x & 31;
    if (lid == 0) sb[wid] = s;
    __syncthreads();
    if (threadIdx.x == 0) {
        float t = 0.f;
        for (int i = 0; i < 8; i++) t += sb[i];
        atomicAdd(&g_ksum, (double)t);
    }
}

// ============================================================================
// Kernel 2: sign(kernel - mean), transposed to [f][d], into TILED+SWIZZLED g_w
// ============================================================================
__global__ void sign_kernel(const float* __restrict__ k) {
    __shared__ float t[32][33];
    float mean = (float)(g_ksum * (1.0 / 16777216.0));
    int d = blockIdx.y * 32 + threadIdx.y;
    int f = blockIdx.x * 32 + threadIdx.x;
    t[threadIdx.y][threadIdx.x] = k[(size_t)d * D_DIM + f];
    __syncthreads();
    int f2 = blockIdx.x * 32 + threadIdx.y;     // output row (n)
    int d2 = blockIdx.y * 32 + threadIdx.x;     // output col (k)
    float v = t[threadIdx.x][threadIdx.y] - mean;
    float s = (v > 0.f) ? 1.f : ((v < 0.f) ? -1.f : 0.f);
    int p  = f2 >> 7, r = f2 & 127;
    int kc = d2 >> 6, w = d2 & 63;
    int u  = w >> 3,  e = w & 7;
    *(__nv_bfloat16*)((char*)g_w + ((size_t)p * KCHUNKS + kc) * BLK_SZ
                      + sw_off(r, u) + e * 2) = __float2bfloat16_rn(s);
}

// ============================================================================
// Kernel 3: per-row RMSNorm + int8 fake-quant -> bf16 TILED+SWIZZLED g_q, 1/sc^2
// ============================================================================
__global__ void quant_kernel(const float* __restrict__ x) {
    int row = blockIdx.x;
    int tid = threadIdx.x;
    const float4* xr = (const float4*)(x + (size_t)row * D_DIM);
    float4 v[4];
    float ss = 0.f, am = 0.f;
#pragma unroll
    for (int i = 0; i < 4; i++) {
        v[i] = xr[tid * 4 + i];
        ss += v[i].x * v[i].x + v[i].y * v[i].y + v[i].z * v[i].z + v[i].w * v[i].w;
        am = fmaxf(am, fmaxf(fmaxf(fabsf(v[i].x), fabsf(v[i].y)),
                             fmaxf(fabsf(v[i].z), fabsf(v[i].w))));
    }
#pragma unroll
    for (int o = 16; o > 0; o >>= 1) {
        ss += __shfl_xor_sync(0xffffffffu, ss, o);
        am = fmaxf(am, __shfl_xor_sync(0xffffffffu, am, o));
    }
    __shared__ float s_ss[8], s_am[8];
    __shared__ float sh_rinv, sh_sc;
    int wid = tid >> 5, lid = tid & 31;
    if (lid == 0) { s_ss[wid] = ss; s_am[wid] = am; }
    __syncthreads();
    if (tid == 0) {
        float t = 0.f, m = 0.f;
        for (int i = 0; i < 8; i++) { t += s_ss[i]; m = fmaxf(m, s_am[i]); }
        float rinv = rsqrtf(t * (1.f / 4096.f) + 1e-5f);
        float amax = m * rinv;                       // == max|x_norm| (monotone)
        float sc = 127.f / fmaxf(amax, 1e-5f);
        sh_rinv = rinv; sh_sc = sc;
        g_rs[row] = 1.f / (sc * sc);
    }
    __syncthreads();
    float rinv = sh_rinv, sc = sh_sc;
    unsigned pk[8];
#pragma unroll
    for (int i = 0; i < 4; i++) {
        float a[4] = { v[i].x, v[i].y, v[i].z, v[i].w };
        unsigned short h[4];
#pragma unroll
        for (int j = 0; j < 4; j++) {
            float xn = a[j] * rinv;
            float r = rintf(xn * sc);                // round half-to-even == jnp.round
            r = fminf(fmaxf(r, -128.f), 127.f);
            h[j] = __bfloat16_as_ushort(__float2bfloat16_rn(r));   // exact
        }
        pk[i * 2]     = (unsigned)h[0] | ((unsigned)h[1] << 16);
        pk[i * 2 + 1] = (unsigned)h[2] | ((unsigned)h[3] << 16);
    }
    int p = row >> 7, r = row & 127;
    int kc = tid >> 2, u0 = (tid & 3) * 2;
    char* base = (char*)g_q + ((size_t)p * KCHUNKS + kc) * BLK_SZ;
    *(uint4*)(base + sw_off(r, u0))     = make_uint4(pk[0], pk[1], pk[2], pk[3]);
    *(uint4*)(base + sw_off(r, u0 + 1)) = make_uint4(pk[4], pk[5], pk[6], pk[7]);
}

// ============================================================================
// Kernel 4: bf16 HMMA GEMM (round-4/12 verified best: 2 CTA/SM, 3-stage ring).
// CTA 128x128, 8 warps (2m x 4n), warp tile 64x32. tid0 drives bulk copies.
// ============================================================================
__global__ void __launch_bounds__(256, 2) gemm_kernel(float* __restrict__ out) {
    extern __shared__ char smem[];
    const uint32_t sbase = smem_to_u32(smem);
    const uint32_t bar   = sbase + BAR_OFF;
    const int tid = threadIdx.x;
    const int wid = tid >> 5, lane = tid & 31;
    const int warp_m = wid >> 2;          // 0..1
    const int warp_n = wid & 3;           // 0..3
    const int m0 = blockIdx.y * TILE_M;
    const int n0 = blockIdx.x * TILE_N;

    const char* gA = (const char*)g_q + (size_t)blockIdx.y * KCHUNKS * BLK_SZ;
    const char* gB = (const char*)g_w + (size_t)blockIdx.x * KCHUNKS * BLK_SZ;

    if (tid == 0) {
#pragma unroll
        for (int s = 0; s < NSTAGE; s++) MBARRIER_INIT(bar + s * 8, 1);
    }
    __syncthreads();

    auto issue = [&](int kc, int s) {
        uint32_t mb = bar + s * 8;
        MBARRIER_ARRIVE_EXPECT_TX(mb, STAGE_SZ);
        cp_bulk(sbase + s * STAGE_SZ,          gA + (size_t)kc * BLK_SZ, BLK_SZ, mb);
        cp_bulk(sbase + s * STAGE_SZ + BLK_SZ, gB + (size_t)kc * BLK_SZ, BLK_SZ, mb);
    };

    if (tid == 0) {
#pragma unroll
        for (int s = 0; s < NSTAGE - 1; s++) issue(s, s);
    }

    float acc[4][4][4];
#pragma unroll
    for (int i = 0; i < 4; i++)
#pragma unroll
        for (int j = 0; j < 4; j++)
#pragma unroll
            for (int c = 0; c < 4; c++) acc[i][j][c] = 0.f;

    const int lr = (lane & 7) + ((lane >> 3) & 1) * 8;   // row within 16-row frag
    const int lk = lane >> 4;                             // which 16B half of k16

    for (int kc = 0; kc < KCHUNKS; kc++) {
        const int s = kc % NSTAGE;
        MBARRIER_WAIT_PARITY(bar + s * 8, (kc / NSTAGE) & 1);

        const uint32_t sa = sbase + s * STAGE_SZ;
        const uint32_t sb = sa + BLK_SZ;

#pragma unroll
        for (int ks = 0; ks < 4; ks++) {              // four k16 steps per 128B chunk
            const int ku = 2 * ks + lk;               // 16B unit index 0..7
            uint32_t afr[4][4];
#pragma unroll
            for (int mf = 0; mf < 4; mf++)
                ldm_x4(afr[mf], sa + sw_off(warp_m * 64 + mf * 16 + lr, ku));
            uint32_t bfr[2][4];
#pragma unroll
            for (int h = 0; h < 2; h++)
                ldm_x4(bfr[h], sb + sw_off(warp_n * 32 + h * 16 + lr, ku));
#pragma unroll
            for (int mf = 0; mf < 4; mf++) {
#pragma unroll
                for (int nf = 0; nf < 4; nf++) {
                    uint32_t b0 = bfr[nf >> 1][nf & 1];
                    uint32_t b1 = bfr[nf >> 1][(nf & 1) + 2];
                    mma_bf16(acc[mf][nf], afr[mf], b0, b1);
                }
            }
        }
        __syncthreads();   // all warps done reading slot s
        if (tid == 0 && kc + NSTAGE - 1 < KCHUNKS)
            issue(kc + NSTAGE - 1, (kc + NSTAGE - 1) % NSTAGE);
    }

    // Epilogue: out = acc * (1/x_scale^2)   (acc holds exact integers in f32)
    const int group = lane >> 2, tig = lane & 3;
#pragma unroll
    for (int mf = 0; mf < 4; mf++) {
        int r0 = m0 + warp_m * 64 + mf * 16 + group;
        float rs0 = g_rs[r0];
        float rs1 = g_rs[r0 + 8];
        float* o0 = out + (size_t)r0 * D_DIM;
        float* o1 = out + (size_t)(r0 + 8) * D_DIM;
#pragma unroll
        for (int nf = 0; nf < 4; nf++) {
            int col = n0 + warp_n * 32 + nf * 8 + tig * 2;
            float2 v0, v1;
            v0.x = acc[mf][nf][0] * rs0;
            v0.y = acc[mf][nf][1] * rs0;
            v1.x = acc[mf][nf][2] * rs1;
            v1.y = acc[mf][nf][3] * rs1;
            *(float2*)(o0 + col) = v0;
            *(float2*)(o1 + col) = v1;
        }
    }
}

// ============================================================================
// kernel_launch: fully sequential. Final configuration — measured optimum
// (R4: 2726.5 us, reproduced R12: 2732.4 us). Closed search: tcgen05 blocked
// at PTX target; all legacy mma kinds rate-pinned; concurrency/persistence/
// micro-variants all measured worse.
// ============================================================================
extern "C" void kernel_launch(void* const* d_in, const int* in_sizes, int n_in,
                              void* d_out, int out_size) {
    const float* x    = (const float*)d_in[0];
    const float* kern = (const float*)d_in[1];
    if (n_in >= 2 && in_sizes[0] < in_sizes[1]) {    // x is the bigger tensor
        x    = (const float*)d_in[1];
        kern = (const float*)d_in[0];
    }

    cudaFuncSetAttribute(gemm_kernel, cudaFuncAttributeMaxDynamicSharedMemorySize, SMEM_BYTES);

    zero_kernel<<<1, 1>>>();
    ksum_kernel<<<1024, 256>>>(kern);
    sign_kernel<<<dim3(D_DIM / 32, D_DIM / 32), dim3(32, 32)>>>(kern);
    quant_kernel<<<M_ROWS, 256>>>(x);
    // grid.x fastest: 32 n-tiles share one A panel; g_w (32MB) stays L2-hot
    gemm_kernel<<<dim3(D_DIM / TILE_N, M_ROWS / TILE_M), 256, SMEM_BYTES>>>((float*)d_out);
}